// round 11
// baseline (speedup 1.0000x reference)
#include <cuda_runtime.h>
#include <cstdint>
#include <cstddef>

#define BB   128
#define SEQ  720
#define PRED 336
#define ENC  321
#define DD   512
#define NG   2048           // 4*D
#define XSTR (SEQ*ENC)
#define KXP  328            // ENC padded to 41*8
#define EPAD 384            // ENC padded for W_pred^T tiles
#define NBLK 128            // persistent grid
#define LSTM_SMEM (32768 + 65536)    // Ws strip 32 KB + 8-slice partials 64 KB

// -------- persistent device scratch --------
__device__ float g_WX  [KXP * NG];        // Wih^T gate-interleaved [k][n], n=d*4+gate
__device__ float g_WE  [DD * NG];         // Whh^T gate-interleaved
__device__ float g_WD  [DD * NG];         // decoder (Wih@Wp + Whh)^T gate-interleaved
__device__ float g_WpT2[DD * EPAD];       // W_pred^T padded [k][e]
__device__ float g_bias [NG];
__device__ float g_biasd[NG];
__device__ float g_hT[2][DD * BB];        // ping-pong hidden state, TRANSPOSED [dim][m]
__device__ float g_xg[(size_t)SEQ * BB * NG];         // precomputed x projections
__device__ float g_hist[(size_t)PRED * BB * DD];      // decoder h_t log ([t][m][dim])

__device__ volatile unsigned g_flag[NBLK * 32];       // spread flags, 128 B apart

// -------- packed fp32x2 FMA --------
__device__ __forceinline__ void fma2(float2 &d, float2 a, float2 b) {
    unsigned long long &du = reinterpret_cast<unsigned long long &>(d);
    unsigned long long au  = reinterpret_cast<unsigned long long &>(a);
    unsigned long long bu  = reinterpret_cast<unsigned long long &>(b);
    asm("fma.rn.f32x2 %0, %1, %2, %0;" : "+l"(du) : "l"(au), "l"(bu));
}

__device__ __forceinline__ float sigm(float x) { return 1.f / (1.f + __expf(-x)); }

// -------- flag-array grid barrier: arrival = STG, detection = parallel polls --------
__device__ __forceinline__ void grid_sync_flag(unsigned target) {
    __threadfence();                       // every thread's h-stores device-visible
    __syncthreads();
    if (threadIdx.x == 0) g_flag[blockIdx.x * 32] = target;
    if (threadIdx.x < NBLK) {
        while (g_flag[threadIdx.x * 32] < target) { }
    }
    __syncthreads();
}

// -------- GEMM micro-kernel pieces (xg_proj / final_pred) --------
struct Slots { int klp[4], mmp[4], kwp[4], nlp[4]; };

__device__ __forceinline__ void make_slots(Slots &s, int tid) {
#pragma unroll
    for (int p = 0; p < 4; ++p) {
        int lin = tid + p * 256;
        s.klp[p] = lin & 7;   s.mmp[p] = lin >> 3;
        s.nlp[p] = lin & 127; s.kwp[p] = lin >> 7;
    }
}

__device__ __forceinline__ void stage(const Slots &s, const float *ur, const float *wr,
                                      float *U, float *W) {
#pragma unroll
    for (int p = 0; p < 4; ++p) {
        U[s.klp[p] * 132 + s.mmp[p]] = ur[p];
        W[s.kwp[p] * 128 + s.nlp[p]] = wr[p];
    }
}

__device__ __forceinline__ void mma8(float2 acc[8][4], const float *U, const float *W,
                                     int tm8, int tn8) {
#pragma unroll
    for (int q = 0; q < 8; ++q) {
        const float4 a0 = *(const float4 *)&U[q * 132 + tm8];
        const float4 a1 = *(const float4 *)&U[q * 132 + tm8 + 4];
        const float4 b0 = *(const float4 *)&W[q * 128 + tn8];
        const float4 b1 = *(const float4 *)&W[q * 128 + tn8 + 4];
        float  av[8] = {a0.x, a0.y, a0.z, a0.w, a1.x, a1.y, a1.z, a1.w};
        float2 bv[4] = {make_float2(b0.x, b0.y), make_float2(b0.z, b0.w),
                        make_float2(b1.x, b1.y), make_float2(b1.z, b1.w)};
#pragma unroll
        for (int r = 0; r < 8; ++r) {
            float2 ad = make_float2(av[r], av[r]);
#pragma unroll
            for (int c = 0; c < 4; ++c) fma2(acc[r][c], ad, bv[c]);
        }
    }
}

// ==================== prep kernels ====================
__global__ void prepA(const float *__restrict__ Wih, const float *__restrict__ Whh,
                      const float *__restrict__ bih, const float *__restrict__ bhh,
                      const float *__restrict__ Wp)
{
    int idx = blockIdx.x * 256 + threadIdx.x;
    if (idx < KXP * NG) {
        int k = idx / NG, n = idx - k * NG, d = n >> 2, gate = n & 3, j = gate * DD + d;
        g_WX[idx] = (k < ENC) ? Wih[(size_t)j * ENC + k] : 0.f;
    }
    if (idx < DD * NG) {
        int k = idx / NG, n = idx - k * NG, d = n >> 2, gate = n & 3, j = gate * DD + d;
        g_WE[idx] = Whh[(size_t)j * DD + k];
    }
    if (idx < DD * EPAD) {
        int k = idx / EPAD, e = idx - k * EPAD;
        g_WpT2[idx] = (e < ENC) ? Wp[(size_t)e * DD + k] : 0.f;
    }
    if (idx < NG) {
        int j = idx, n = (j & 511) * 4 + (j >> 9);
        g_bias[n] = bih[j] + bhh[j];
    }
    if (idx < 2 * BB * DD) ((float *)g_hT)[idx] = 0.f;
    if (idx < NBLK * 32) g_flag[idx] = 0;   // reset barrier flags every launch (graph replay safe)
}

// g_WD[k][n] = sum_e Wih[j][e]*Wp[e][k] + Whh[j][k];  biasd[n] = bias[n] + Wih[j]·bp
__global__ void prepB(const float *__restrict__ Wih, const float *__restrict__ Whh,
                      const float *__restrict__ bp)
{
    __shared__ float sW[EPAD];
    __shared__ float red[128];
    const int j = blockIdx.x, tid = threadIdx.x;
    for (int e = tid; e < EPAD; e += 128) sW[e] = (e < ENC) ? Wih[(size_t)j * ENC + e] : 0.f;
    __syncthreads();
    const int d = j & 511, gate = j >> 9, n = d * 4 + gate;
    for (int k = tid; k < DD; k += 128) {
        float a0 = 0.f, a1 = 0.f, a2 = 0.f, a3 = 0.f;
        const float *wr = &g_WpT2[(size_t)k * EPAD];
        for (int e = 0; e < EPAD; e += 4) {
            const float4 wv = *(const float4 *)&wr[e];
            const float4 sv = *(const float4 *)&sW[e];
            a0 += sv.x * wv.x; a1 += sv.y * wv.y; a2 += sv.z * wv.z; a3 += sv.w * wv.w;
        }
        g_WD[(size_t)k * NG + n] = (a0 + a1) + (a2 + a3) + Whh[(size_t)j * DD + k];
    }
    float p = 0.f;
    for (int e = tid; e < ENC; e += 128) p += sW[e] * bp[e];
    red[tid] = p; __syncthreads();
    for (int off = 64; off; off >>= 1) { if (tid < off) red[tid] += red[tid + off]; __syncthreads(); }
    if (tid == 0) g_biasd[n] = g_bias[n] + red[0];
}

// ==================== parallel input projection: xg[t][b][n] ====================
__global__ __launch_bounds__(256) void xg_proj(const float *__restrict__ x)
{
    __shared__ float Us[2][8 * 132];
    __shared__ float Ws[2][8 * 128];
    const int t = blockIdx.y, nbase = blockIdx.x * 128, tid = threadIdx.x;
    const int tm8 = (tid >> 4) * 8, tn8 = (tid & 15) * 8;
    const float *xbase = x + (size_t)t * ENC;

    Slots s; make_slots(s, tid);
    float2 acc[8][4];
#pragma unroll
    for (int r = 0; r < 8; ++r)
#pragma unroll
        for (int c = 0; c < 4; ++c) acc[r][c] = make_float2(0.f, 0.f);

    float ur[4], wr[4];
    auto load = [&](int kb) {
#pragma unroll
        for (int p = 0; p < 4; ++p) {
            int k = kb + s.klp[p];
            ur[p] = (k < ENC) ? __ldg(&xbase[(size_t)s.mmp[p] * XSTR + k]) : 0.f;
            wr[p] = g_WX[(size_t)(kb + s.kwp[p]) * NG + nbase + s.nlp[p]];
        }
    };

    int buf = 0;
    load(0);
    stage(s, ur, wr, Us[0], Ws[0]);
    __syncthreads();
#pragma unroll 1
    for (int c8 = 0; c8 < 41; ++c8) {
        if (c8 < 40) load((c8 + 1) * 8);
        mma8(acc, Us[buf], Ws[buf], tm8, tn8);
        if (c8 < 40) { stage(s, ur, wr, Us[buf ^ 1], Ws[buf ^ 1]); __syncthreads(); buf ^= 1; }
    }
#pragma unroll
    for (int r = 0; r < 8; ++r) {
        float *dst = &g_xg[((size_t)t * BB + tm8 + r) * NG + nbase + tn8];
        *(float4 *)dst       = make_float4(acc[r][0].x, acc[r][0].y, acc[r][1].x, acc[r][1].y);
        *(float4 *)(dst + 4) = make_float4(acc[r][2].x, acc[r][2].y, acc[r][3].x, acc[r][3].y);
    }
}

// ==================== persistent recurrent kernel ====================
// 128 blocks x 1024 threads (32 warps, 8/SMSP). Block bx owns gate-cols
// [16bx,16bx+16) == dims [4bx,4bx+4). Warp w = (k-slice ks = w&7 of 64 dims,
// m-quarter mq = w>>3 of 32 batches); lane owns ONE m row (scalar A loads,
// coalesced 128B per warp, straight from transposed h in L2).
// Partials: [8][128][16] = 64 KB smem, reduced once; thread tid<512 owns one
// cell (m = tid&127, dl = (tid>>7)&3) with c resident in a register.
// One flag-array grid barrier per step; no other global sync.
__global__ __launch_bounds__(1024, 1) void lstm_persistent()
{
    extern __shared__ float dsm[];
    float *Ws   = dsm;                  // [512][16]  weight strip, 32 KB
    float *part = dsm + DD * 16;        // [8][128][16] partials, 64 KB

    const int tid = threadIdx.x, bx = blockIdx.x;
    const int w = tid >> 5, lane = tid & 31;
    const int ks = w & 7, mq = w >> 3;
    const int k0 = ks * 64;
    const int mg = mq * 32 + lane;      // GEMM row (batch) this lane computes

    const int dl = (tid >> 7) & 3;      // cell dim within block (tid < 512)
    const int mo = tid & 127;           // cell batch

    // step-invariant addressing
    const int aoff = k0 * BB + mg;
    float *stp = &part[ks * 2048 + mg * 16];
    const int ssw = ((mg >> 1) ^ (mg >> 2)) & 3;
    const float *rptr = &part[mo * 16 + (dl ^ (((mo >> 1) ^ (mo >> 2)) & 3)) * 4];

    for (int i = tid; i < DD * 16; i += 1024)
        Ws[i] = g_WE[(size_t)(i >> 4) * NG + bx * 16 + (i & 15)];
    float4 bias = make_float4(0.f, 0.f, 0.f, 0.f);
    if (tid < 512) bias = *(const float4 *)&g_bias[bx * 16 + 4 * dl];
    float cst = 0.f;
    __syncthreads();

    for (int st = 0; st < SEQ + PRED - 1; ++st) {
        const bool enc = (st < SEQ);
        if (st == SEQ) {                 // switch to decoder weights
            for (int i = tid; i < DD * 16; i += 1024)
                Ws[i] = g_WD[(size_t)(i >> 4) * NG + bx * 16 + (i & 15)];
            if (tid < 512) bias = *(const float4 *)&g_biasd[bx * 16 + 4 * dl];
            __syncthreads();
        }
        const float *hb = g_hT[st & 1] + aoff;
        float *hw = g_hT[(st & 1) ^ 1];

        // prefetch xg for this thread's cell — consumed after the GEMM
        float4 xa = make_float4(0.f, 0.f, 0.f, 0.f);
        if (enc && tid < 512)
            xa = __ldcg((const float4 *)&g_xg[((size_t)st * BB + mo) * NG + bx * 16 + 4 * dl]);

        // ---- GEMM: acc[c] += h[mg][k] * W[k][2c..2c+2), k in this warp's slice
        float2 acc[8];
#pragma unroll
        for (int c = 0; c < 8; ++c) acc[c] = make_float2(0.f, 0.f);

        float pf[8];
#pragma unroll
        for (int j = 0; j < 8; ++j) pf[j] = __ldcg(hb + j * BB);

        const float4 *wp = (const float4 *)&Ws[k0 * 16];
#pragma unroll 8
        for (int k = 0; k < 64; ++k) {
            float a = pf[k & 7];
            pf[k & 7] = __ldcg(hb + ((k + 8) & 63) * BB);   // wrap: tail reloads, harmless
            const float4 w0 = wp[k * 4 + 0], w1 = wp[k * 4 + 1];
            const float4 w2 = wp[k * 4 + 2], w3 = wp[k * 4 + 3];
            float2 aa = make_float2(a, a);
            fma2(acc[0], aa, make_float2(w0.x, w0.y));
            fma2(acc[1], aa, make_float2(w0.z, w0.w));
            fma2(acc[2], aa, make_float2(w1.x, w1.y));
            fma2(acc[3], aa, make_float2(w1.z, w1.w));
            fma2(acc[4], aa, make_float2(w2.x, w2.y));
            fma2(acc[5], aa, make_float2(w2.z, w2.w));
            fma2(acc[6], aa, make_float2(w3.x, w3.y));
            fma2(acc[7], aa, make_float2(w3.z, w3.w));
        }

        // ---- store partials (swizzled so reduce reads stay spread)
#pragma unroll
        for (int c4 = 0; c4 < 4; ++c4) {
            float4 v = make_float4(acc[2 * c4].x,     acc[2 * c4].y,
                                   acc[2 * c4 + 1].x, acc[2 * c4 + 1].y);
            *(float4 *)(stp + (c4 ^ ssw) * 4) = v;
        }
        __syncthreads();

        // ---- reduce 8 partials + cell update (one cell per thread, tid<512)
        if (tid < 512) {
            float4 s = make_float4(0.f, 0.f, 0.f, 0.f);
#pragma unroll
            for (int ww = 0; ww < 8; ++ww) {
                const float4 v = *(const float4 *)(rptr + ww * 2048);
                s.x += v.x; s.y += v.y; s.z += v.z; s.w += v.w;
            }
            float gi = s.x + bias.x + xa.x;
            float gf = s.y + bias.y + xa.y;
            float gg = s.z + bias.z + xa.z;
            float go = s.w + bias.w + xa.w;
            float cn = sigm(gf) * cst + sigm(gi) * tanhf(gg);
            cst = cn;
            float h0 = sigm(go) * tanhf(cn);
            hw[(4 * bx + dl) * BB + mo] = h0;
            if (!enc)
                g_hist[(size_t)(st - SEQ + 1) * BB * DD + (size_t)mo * DD + 4 * bx + dl] = h0;
            else if (st == SEQ - 1)
                g_hist[(size_t)mo * DD + 4 * bx + dl] = h0;
        }
        grid_sync_flag((unsigned)(st + 1));    // also fences part/Ws reuse next step
    }
}

// ==================== batched output projection ====================
__global__ __launch_bounds__(256) void final_pred(const float *__restrict__ bp,
                                                  float *__restrict__ out)
{
    __shared__ float As[2][8 * 132];
    __shared__ float Bs[2][8 * 128];
    const int t = blockIdx.y, ebase = blockIdx.x * 128, tid = threadIdx.x;
    const int tm8 = (tid >> 4) * 8, tn8 = (tid & 15) * 8;
    const float *A = g_hist + (size_t)t * BB * DD;

    Slots s; make_slots(s, tid);
    float2 acc[8][4];
#pragma unroll
    for (int r = 0; r < 8; ++r)
#pragma unroll
        for (int c = 0; c < 4; ++c) acc[r][c] = make_float2(0.f, 0.f);

    float ar[4], br[4];
    auto load = [&](int kb) {
#pragma unroll
        for (int p = 0; p < 4; ++p) {
            ar[p] = A[(size_t)s.mmp[p] * DD + kb + s.klp[p]];
            br[p] = g_WpT2[(size_t)(kb + s.kwp[p]) * EPAD + ebase + s.nlp[p]];
        }
    };

    int buf = 0;
    load(0);
    stage(s, ar, br, As[0], Bs[0]);
    __syncthreads();
#pragma unroll 1
    for (int c8 = 0; c8 < 64; ++c8) {
        if (c8 < 63) load((c8 + 1) * 8);
        mma8(acc, As[buf], Bs[buf], tm8, tn8);
        if (c8 < 63) { stage(s, ar, br, As[buf ^ 1], Bs[buf ^ 1]); __syncthreads(); buf ^= 1; }
    }
#pragma unroll
    for (int r = 0; r < 8; ++r) {
        int b = tm8 + r;
        float *orow = out + ((size_t)b * PRED + t) * ENC;
        float vals[8] = {acc[r][0].x, acc[r][0].y, acc[r][1].x, acc[r][1].y,
                         acc[r][2].x, acc[r][2].y, acc[r][3].x, acc[r][3].y};
#pragma unroll
        for (int c = 0; c < 8; ++c) {
            int e = ebase + tn8 + c;
            if (e < ENC) orow[e] = vals[c] + bp[e];
        }
    }
}

extern "C" void kernel_launch(void *const *d_in, const int *in_sizes, int n_in,
                              void *d_out, int out_size)
{
    const float *x   = (const float *)d_in[0];
    const float *Wih = (const float *)d_in[1];
    const float *Whh = (const float *)d_in[2];
    const float *bih = (const float *)d_in[3];
    const float *bhh = (const float *)d_in[4];
    const float *Wp  = (const float *)d_in[5];
    const float *bp  = (const float *)d_in[6];
    float *out = (float *)d_out;

    cudaFuncSetAttribute(lstm_persistent,
                         cudaFuncAttributeMaxDynamicSharedMemorySize, LSTM_SMEM);

    prepA<<<4096, 256>>>(Wih, Whh, bih, bhh, Wp);
    prepB<<<NG, 128>>>(Wih, Whh, bp);
    xg_proj<<<dim3(16, SEQ), 256>>>(x);
    lstm_persistent<<<NBLK, 1024, LSTM_SMEM>>>();
    final_pred<<<dim3(3, PRED), 256>>>(bp, out);
}

// round 12
// speedup vs baseline: 1.0941x; 1.0941x over previous
#include <cuda_runtime.h>
#include <cstdint>
#include <cstddef>

#define BB   128
#define SEQ  720
#define PRED 336
#define ENC  321
#define DD   512
#define NG   2048           // 4*D
#define XSTR (SEQ*ENC)
#define KXP  328            // ENC padded to 41*8
#define EPAD 384            // ENC padded for W_pred^T tiles
#define NBLK 128            // persistent grid
#define LSTM_SMEM (32768 + 131072)   // Ws strip 32 KB + 16-slice partials 128 KB

// -------- persistent device scratch --------
__device__ float g_WX  [KXP * NG];        // Wih^T gate-interleaved [k][n], n=d*4+gate
__device__ float g_WE  [DD * NG];         // Whh^T gate-interleaved
__device__ float g_WD  [DD * NG];         // decoder (Wih@Wp + Whh)^T gate-interleaved
__device__ float g_WpT2[DD * EPAD];       // W_pred^T padded [k][e]
__device__ float g_bias [NG];
__device__ float g_biasd[NG];
__device__ float g_hT[2][DD * BB];        // ping-pong hidden state, TRANSPOSED [dim][m]
__device__ float g_xg[(size_t)SEQ * BB * NG];         // precomputed x projections
__device__ float g_hist[(size_t)PRED * BB * DD];      // decoder h_t log ([t][m][dim])

__device__ volatile unsigned g_flag[NBLK * 32];       // spread flags, 128 B apart

// -------- packed fp32x2 FMA --------
__device__ __forceinline__ void fma2(float2 &d, float2 a, float2 b) {
    unsigned long long &du = reinterpret_cast<unsigned long long &>(d);
    unsigned long long au  = reinterpret_cast<unsigned long long &>(a);
    unsigned long long bu  = reinterpret_cast<unsigned long long &>(b);
    asm("fma.rn.f32x2 %0, %1, %2, %0;" : "+l"(du) : "l"(au), "l"(bu));
}

__device__ __forceinline__ float sigm(float x) { return 1.f / (1.f + __expf(-x)); }

// -------- flag-array grid barrier: arrival = STG, detection = parallel polls --------
__device__ __forceinline__ void grid_sync_flag(unsigned target) {
    __threadfence();                       // every thread's h-stores device-visible
    __syncthreads();
    if (threadIdx.x == 0) g_flag[blockIdx.x * 32] = target;
    if (threadIdx.x < NBLK) {
        while (g_flag[threadIdx.x * 32] < target) { }
    }
    __syncthreads();
}

// -------- GEMM micro-kernel pieces (xg_proj / final_pred) --------
struct Slots { int klp[4], mmp[4], kwp[4], nlp[4]; };

__device__ __forceinline__ void make_slots(Slots &s, int tid) {
#pragma unroll
    for (int p = 0; p < 4; ++p) {
        int lin = tid + p * 256;
        s.klp[p] = lin & 7;   s.mmp[p] = lin >> 3;
        s.nlp[p] = lin & 127; s.kwp[p] = lin >> 7;
    }
}

__device__ __forceinline__ void stage(const Slots &s, const float *ur, const float *wr,
                                      float *U, float *W) {
#pragma unroll
    for (int p = 0; p < 4; ++p) {
        U[s.klp[p] * 132 + s.mmp[p]] = ur[p];
        W[s.kwp[p] * 128 + s.nlp[p]] = wr[p];
    }
}

__device__ __forceinline__ void mma8(float2 acc[8][4], const float *U, const float *W,
                                     int tm8, int tn8) {
#pragma unroll
    for (int q = 0; q < 8; ++q) {
        const float4 a0 = *(const float4 *)&U[q * 132 + tm8];
        const float4 a1 = *(const float4 *)&U[q * 132 + tm8 + 4];
        const float4 b0 = *(const float4 *)&W[q * 128 + tn8];
        const float4 b1 = *(const float4 *)&W[q * 128 + tn8 + 4];
        float  av[8] = {a0.x, a0.y, a0.z, a0.w, a1.x, a1.y, a1.z, a1.w};
        float2 bv[4] = {make_float2(b0.x, b0.y), make_float2(b0.z, b0.w),
                        make_float2(b1.x, b1.y), make_float2(b1.z, b1.w)};
#pragma unroll
        for (int r = 0; r < 8; ++r) {
            float2 ad = make_float2(av[r], av[r]);
#pragma unroll
            for (int c = 0; c < 4; ++c) fma2(acc[r][c], ad, bv[c]);
        }
    }
}

// ==================== prep kernels ====================
__global__ void prepA(const float *__restrict__ Wih, const float *__restrict__ Whh,
                      const float *__restrict__ bih, const float *__restrict__ bhh,
                      const float *__restrict__ Wp)
{
    int idx = blockIdx.x * 256 + threadIdx.x;
    if (idx < KXP * NG) {
        int k = idx / NG, n = idx - k * NG, d = n >> 2, gate = n & 3, j = gate * DD + d;
        g_WX[idx] = (k < ENC) ? Wih[(size_t)j * ENC + k] : 0.f;
    }
    if (idx < DD * NG) {
        int k = idx / NG, n = idx - k * NG, d = n >> 2, gate = n & 3, j = gate * DD + d;
        g_WE[idx] = Whh[(size_t)j * DD + k];
    }
    if (idx < DD * EPAD) {
        int k = idx / EPAD, e = idx - k * EPAD;
        g_WpT2[idx] = (e < ENC) ? Wp[(size_t)e * DD + k] : 0.f;
    }
    if (idx < NG) {
        int j = idx, n = (j & 511) * 4 + (j >> 9);
        g_bias[n] = bih[j] + bhh[j];
    }
    if (idx < 2 * BB * DD) ((float *)g_hT)[idx] = 0.f;
    if (idx < NBLK * 32) g_flag[idx] = 0;   // reset barrier flags every launch (graph replay safe)
}

// g_WD[k][n] = sum_e Wih[j][e]*Wp[e][k] + Whh[j][k];  biasd[n] = bias[n] + Wih[j]·bp
__global__ void prepB(const float *__restrict__ Wih, const float *__restrict__ Whh,
                      const float *__restrict__ bp)
{
    __shared__ float sW[EPAD];
    __shared__ float red[128];
    const int j = blockIdx.x, tid = threadIdx.x;
    for (int e = tid; e < EPAD; e += 128) sW[e] = (e < ENC) ? Wih[(size_t)j * ENC + e] : 0.f;
    __syncthreads();
    const int d = j & 511, gate = j >> 9, n = d * 4 + gate;
    for (int k = tid; k < DD; k += 128) {
        float a0 = 0.f, a1 = 0.f, a2 = 0.f, a3 = 0.f;
        const float *wr = &g_WpT2[(size_t)k * EPAD];
        for (int e = 0; e < EPAD; e += 4) {
            const float4 wv = *(const float4 *)&wr[e];
            const float4 sv = *(const float4 *)&sW[e];
            a0 += sv.x * wv.x; a1 += sv.y * wv.y; a2 += sv.z * wv.z; a3 += sv.w * wv.w;
        }
        g_WD[(size_t)k * NG + n] = (a0 + a1) + (a2 + a3) + Whh[(size_t)j * DD + k];
    }
    float p = 0.f;
    for (int e = tid; e < ENC; e += 128) p += sW[e] * bp[e];
    red[tid] = p; __syncthreads();
    for (int off = 64; off; off >>= 1) { if (tid < off) red[tid] += red[tid + off]; __syncthreads(); }
    if (tid == 0) g_biasd[n] = g_bias[n] + red[0];
}

// ==================== parallel input projection: xg[t][b][n] ====================
__global__ __launch_bounds__(256) void xg_proj(const float *__restrict__ x)
{
    __shared__ float Us[2][8 * 132];
    __shared__ float Ws[2][8 * 128];
    const int t = blockIdx.y, nbase = blockIdx.x * 128, tid = threadIdx.x;
    const int tm8 = (tid >> 4) * 8, tn8 = (tid & 15) * 8;
    const float *xbase = x + (size_t)t * ENC;

    Slots s; make_slots(s, tid);
    float2 acc[8][4];
#pragma unroll
    for (int r = 0; r < 8; ++r)
#pragma unroll
        for (int c = 0; c < 4; ++c) acc[r][c] = make_float2(0.f, 0.f);

    float ur[4], wr[4];
    auto load = [&](int kb) {
#pragma unroll
        for (int p = 0; p < 4; ++p) {
            int k = kb + s.klp[p];
            ur[p] = (k < ENC) ? __ldg(&xbase[(size_t)s.mmp[p] * XSTR + k]) : 0.f;
            wr[p] = g_WX[(size_t)(kb + s.kwp[p]) * NG + nbase + s.nlp[p]];
        }
    };

    int buf = 0;
    load(0);
    stage(s, ur, wr, Us[0], Ws[0]);
    __syncthreads();
#pragma unroll 1
    for (int c8 = 0; c8 < 41; ++c8) {
        if (c8 < 40) load((c8 + 1) * 8);
        mma8(acc, Us[buf], Ws[buf], tm8, tn8);
        if (c8 < 40) { stage(s, ur, wr, Us[buf ^ 1], Ws[buf ^ 1]); __syncthreads(); buf ^= 1; }
    }
#pragma unroll
    for (int r = 0; r < 8; ++r) {
        float *dst = &g_xg[((size_t)t * BB + tm8 + r) * NG + nbase + tn8];
        *(float4 *)dst       = make_float4(acc[r][0].x, acc[r][0].y, acc[r][1].x, acc[r][1].y);
        *(float4 *)(dst + 4) = make_float4(acc[r][2].x, acc[r][2].y, acc[r][3].x, acc[r][3].y);
    }
}

// ==================== persistent recurrent kernel ====================
// 128 blocks x 1024 threads (32 warps, 8/SMSP). Block bx owns gate-cols
// [16bx,16bx+16) == dims [4bx,4bx+4). Warp w = (k-slice ks = w>>1 of 32 dims,
// m-half mh = w&1 of 64 batches). Lane owns TWO m rows (one float2 A-load per
// k, coalesced, straight from transposed h in L2). No (k,m) duplication and
// only 2 m-partitions -> weight smem reads stay amortized (4096 LDS/SM/step).
// Partials: [16][128][16] = 128 KB smem, reduced once; thread tid<512 owns one
// cell (m = tid&127, dl = (tid>>7)&3) with c resident in a register.
// One flag-array grid barrier per step; no other global sync.
__global__ __launch_bounds__(1024, 1) void lstm_persistent()
{
    extern __shared__ float dsm[];
    float *Ws   = dsm;                  // [512][16]  weight strip, 32 KB
    float *part = dsm + DD * 16;        // [16][128][16] partials, 128 KB

    const int tid = threadIdx.x, bx = blockIdx.x;
    const int w = tid >> 5, lane = tid & 31;
    const int ks = w >> 1, mh = w & 1;
    const int k0 = ks * 32;
    const int mg = mh * 64 + 2 * lane;  // first of this lane's two batch rows

    const int dl = (tid >> 7) & 3;      // cell dim within block (tid < 512)
    const int mo = tid & 127;           // cell batch

    // step-invariant addressing
    const int aoff = k0 * BB + mg;
    float *stp0 = &part[ks * 2048 + mg * 16];
    const int ssw0 = ((mg >> 1) ^ (mg >> 2)) & 3;
    const int mg1 = mg + 1;
    const int ssw1 = ((mg1 >> 1) ^ (mg1 >> 2)) & 3;
    const float *rptr = &part[mo * 16 + (dl ^ (((mo >> 1) ^ (mo >> 2)) & 3)) * 4];

    for (int i = tid; i < DD * 16; i += 1024)
        Ws[i] = g_WE[(size_t)(i >> 4) * NG + bx * 16 + (i & 15)];
    float4 bias = make_float4(0.f, 0.f, 0.f, 0.f);
    if (tid < 512) bias = *(const float4 *)&g_bias[bx * 16 + 4 * dl];
    float cst = 0.f;
    __syncthreads();

    for (int st = 0; st < SEQ + PRED - 1; ++st) {
        const bool enc = (st < SEQ);
        if (st == SEQ) {                 // switch to decoder weights
            for (int i = tid; i < DD * 16; i += 1024)
                Ws[i] = g_WD[(size_t)(i >> 4) * NG + bx * 16 + (i & 15)];
            if (tid < 512) bias = *(const float4 *)&g_biasd[bx * 16 + 4 * dl];
            __syncthreads();
        }
        const float *hb = g_hT[st & 1] + aoff;
        float *hw = g_hT[(st & 1) ^ 1];

        // ---- GEMM: acc[i][c] += h[mg+i][k] * W[k][2c..2c+2), k in warp's slice
        float2 acc[2][8];
#pragma unroll
        for (int i = 0; i < 2; ++i)
#pragma unroll
            for (int c = 0; c < 8; ++c) acc[i][c] = make_float2(0.f, 0.f);

        float2 pf[4];
#pragma unroll
        for (int j = 0; j < 4; ++j)
            pf[j] = __ldcg((const float2 *)(hb + j * BB));

        const float4 *wp = (const float4 *)&Ws[k0 * 16];
#pragma unroll 4
        for (int k = 0; k < 32; ++k) {
            float2 a = pf[k & 3];
            pf[k & 3] = __ldcg((const float2 *)(hb + ((k + 4) & 31) * BB)); // wrap: tail reloads
            float2 a0 = make_float2(a.x, a.x);
            float2 a1 = make_float2(a.y, a.y);
            {   // cols 0..7
                const float4 w0 = wp[k * 4 + 0], w1 = wp[k * 4 + 1];
                fma2(acc[0][0], a0, make_float2(w0.x, w0.y));
                fma2(acc[0][1], a0, make_float2(w0.z, w0.w));
                fma2(acc[0][2], a0, make_float2(w1.x, w1.y));
                fma2(acc[0][3], a0, make_float2(w1.z, w1.w));
                fma2(acc[1][0], a1, make_float2(w0.x, w0.y));
                fma2(acc[1][1], a1, make_float2(w0.z, w0.w));
                fma2(acc[1][2], a1, make_float2(w1.x, w1.y));
                fma2(acc[1][3], a1, make_float2(w1.z, w1.w));
            }
            {   // cols 8..15
                const float4 w2 = wp[k * 4 + 2], w3 = wp[k * 4 + 3];
                fma2(acc[0][4], a0, make_float2(w2.x, w2.y));
                fma2(acc[0][5], a0, make_float2(w2.z, w2.w));
                fma2(acc[0][6], a0, make_float2(w3.x, w3.y));
                fma2(acc[0][7], a0, make_float2(w3.z, w3.w));
                fma2(acc[1][4], a1, make_float2(w2.x, w2.y));
                fma2(acc[1][5], a1, make_float2(w2.z, w2.w));
                fma2(acc[1][6], a1, make_float2(w3.x, w3.y));
                fma2(acc[1][7], a1, make_float2(w3.z, w3.w));
            }
        }

        // ---- store partials (swizzled so reduce reads stay spread)
#pragma unroll
        for (int c4 = 0; c4 < 4; ++c4) {
            float4 v0 = make_float4(acc[0][2 * c4].x,     acc[0][2 * c4].y,
                                    acc[0][2 * c4 + 1].x, acc[0][2 * c4 + 1].y);
            *(float4 *)(stp0 + (c4 ^ ssw0) * 4) = v0;
        }
#pragma unroll
        for (int c4 = 0; c4 < 4; ++c4) {
            float4 v1 = make_float4(acc[1][2 * c4].x,     acc[1][2 * c4].y,
                                    acc[1][2 * c4 + 1].x, acc[1][2 * c4 + 1].y);
            *(float4 *)(stp0 + 16 + (c4 ^ ssw1) * 4) = v1;
        }
        __syncthreads();

        // ---- reduce 16 partials + cell update (one cell per thread, tid<512)
        if (tid < 512) {
            // xg load issued here (off the k-loop's register live range)
            float4 xa = make_float4(0.f, 0.f, 0.f, 0.f);
            if (enc)
                xa = __ldcg((const float4 *)&g_xg[((size_t)st * BB + mo) * NG + bx * 16 + 4 * dl]);
            float4 s = make_float4(0.f, 0.f, 0.f, 0.f);
#pragma unroll
            for (int ww = 0; ww < 16; ++ww) {
                const float4 v = *(const float4 *)(rptr + ww * 2048);
                s.x += v.x; s.y += v.y; s.z += v.z; s.w += v.w;
            }
            float gi = s.x + bias.x + xa.x;
            float gf = s.y + bias.y + xa.y;
            float gg = s.z + bias.z + xa.z;
            float go = s.w + bias.w + xa.w;
            float cn = sigm(gf) * cst + sigm(gi) * tanhf(gg);
            cst = cn;
            float h0 = sigm(go) * tanhf(cn);
            hw[(4 * bx + dl) * BB + mo] = h0;
            if (!enc)
                g_hist[(size_t)(st - SEQ + 1) * BB * DD + (size_t)mo * DD + 4 * bx + dl] = h0;
            else if (st == SEQ - 1)
                g_hist[(size_t)mo * DD + 4 * bx + dl] = h0;
        }
        grid_sync_flag((unsigned)(st + 1));    // also fences part/Ws reuse next step
    }
}

// ==================== batched output projection ====================
__global__ __launch_bounds__(256) void final_pred(const float *__restrict__ bp,
                                                  float *__restrict__ out)
{
    __shared__ float As[2][8 * 132];
    __shared__ float Bs[2][8 * 128];
    const int t = blockIdx.y, ebase = blockIdx.x * 128, tid = threadIdx.x;
    const int tm8 = (tid >> 4) * 8, tn8 = (tid & 15) * 8;
    const float *A = g_hist + (size_t)t * BB * DD;

    Slots s; make_slots(s, tid);
    float2 acc[8][4];
#pragma unroll
    for (int r = 0; r < 8; ++r)
#pragma unroll
        for (int c = 0; c < 4; ++c) acc[r][c] = make_float2(0.f, 0.f);

    float ar[4], br[4];
    auto load = [&](int kb) {
#pragma unroll
        for (int p = 0; p < 4; ++p) {
            ar[p] = A[(size_t)s.mmp[p] * DD + kb + s.klp[p]];
            br[p] = g_WpT2[(size_t)(kb + s.kwp[p]) * EPAD + ebase + s.nlp[p]];
        }
    };

    int buf = 0;
    load(0);
    stage(s, ar, br, As[0], Bs[0]);
    __syncthreads();
#pragma unroll 1
    for (int c8 = 0; c8 < 64; ++c8) {
        if (c8 < 63) load((c8 + 1) * 8);
        mma8(acc, As[buf], Bs[buf], tm8, tn8);
        if (c8 < 63) { stage(s, ar, br, As[buf ^ 1], Bs[buf ^ 1]); __syncthreads(); buf ^= 1; }
    }
#pragma unroll
    for (int r = 0; r < 8; ++r) {
        int b = tm8 + r;
        float *orow = out + ((size_t)b * PRED + t) * ENC;
        float vals[8] = {acc[r][0].x, acc[r][0].y, acc[r][1].x, acc[r][1].y,
                         acc[r][2].x, acc[r][2].y, acc[r][3].x, acc[r][3].y};
#pragma unroll
        for (int c = 0; c < 8; ++c) {
            int e = ebase + tn8 + c;
            if (e < ENC) orow[e] = vals[c] + bp[e];
        }
    }
}

extern "C" void kernel_launch(void *const *d_in, const int *in_sizes, int n_in,
                              void *d_out, int out_size)
{
    const float *x   = (const float *)d_in[0];
    const float *Wih = (const float *)d_in[1];
    const float *Whh = (const float *)d_in[2];
    const float *bih = (const float *)d_in[3];
    const float *bhh = (const float *)d_in[4];
    const float *Wp  = (const float *)d_in[5];
    const float *bp  = (const float *)d_in[6];
    float *out = (float *)d_out;

    cudaFuncSetAttribute(lstm_persistent,
                         cudaFuncAttributeMaxDynamicSharedMemorySize, LSTM_SMEM);

    prepA<<<4096, 256>>>(Wih, Whh, bih, bhh, Wp);
    prepB<<<NG, 128>>>(Wih, Whh, bp);
    xg_proj<<<dim3(16, SEQ), 256>>>(x);
    lstm_persistent<<<NBLK, 1024, LSTM_SMEM>>>();
    final_pred<<<dim3(3, PRED), 256>>>(bp, out);
}